// round 3
// baseline (speedup 1.0000x reference)
#include <cuda_runtime.h>
#include <math.h>

// Problem-fixed sizes: N=100000, E=1600000, D=128, EIG=32.
#define MAXN 100000
#define MAXE 1600000
#define FULLMASK 0xffffffffu

// Scratch (device globals — no allocation allowed).
__device__ float g_me[MAXN];        // per-node motif embedding value
__device__ int   g_cnt[MAXN];       // histogram, then scatter cursor
__device__ int   g_off[MAXN + 1];   // CSR row offsets
__device__ float g_acc[3];          // sum(ab), sum(a2), sum(b2)
__device__ float g_par[2];          // [0]=exp(lambda0), [1]=c = gamma*sim
__device__ int2  g_edge[MAXE];      // (col, adj-as-int) sorted by row

// ---------------------------------------------------------------------------
// K0: zero counters/accumulators, compute me[n] = motif_emb_w[motif_ids[n]]
// ---------------------------------------------------------------------------
__global__ void k_init(const float* __restrict__ memb,
                       const int* __restrict__ mids, int n) {
    int i = blockIdx.x * blockDim.x + threadIdx.x;
    if (i == 0) { g_acc[0] = 0.f; g_acc[1] = 0.f; g_acc[2] = 0.f; }
    if (i < n) {
        g_me[i]  = memb[mids[i]];
        g_cnt[i] = 0;
    }
}

// ---------------------------------------------------------------------------
// K1: edge-level scalar reductions (for cosine sim) + row histogram
// ---------------------------------------------------------------------------
__global__ void k_edge1(const int* __restrict__ row,
                        const int* __restrict__ col, int e) {
    float pab = 0.f, pa2 = 0.f, pb2 = 0.f;
    for (int i = blockIdx.x * blockDim.x + threadIdx.x; i < e;
         i += gridDim.x * blockDim.x) {
        int r = row[i], c = col[i];
        atomicAdd(&g_cnt[r], 1);
        float a = g_me[r], b = g_me[c];
        pab = fmaf(a, b, pab);
        pa2 = fmaf(a, a, pa2);
        pb2 = fmaf(b, b, pb2);
    }
#pragma unroll
    for (int o = 16; o; o >>= 1) {
        pab += __shfl_down_sync(FULLMASK, pab, o);
        pa2 += __shfl_down_sync(FULLMASK, pa2, o);
        pb2 += __shfl_down_sync(FULLMASK, pb2, o);
    }
    __shared__ float sb[3][8];
    int w = threadIdx.x >> 5, l = threadIdx.x & 31;
    if (!l) { sb[0][w] = pab; sb[1][w] = pa2; sb[2][w] = pb2; }
    __syncthreads();
    if (!threadIdx.x) {
        float t0 = 0.f, t1 = 0.f, t2 = 0.f;
        int nw = blockDim.x >> 5;
        for (int j = 0; j < nw; j++) { t0 += sb[0][j]; t1 += sb[1][j]; t2 += sb[2][j]; }
        atomicAdd(&g_acc[0], t0);
        atomicAdd(&g_acc[1], t1);
        atomicAdd(&g_acc[2], t2);
    }
}

// ---------------------------------------------------------------------------
// K2: exclusive scan of histogram -> CSR offsets + cursor; compute scalars
// ---------------------------------------------------------------------------
__global__ void k_scan(const float* __restrict__ lambda0,
                       const float* __restrict__ gamma, int n, int e) {
    __shared__ int ssum[1024];
    int t = threadIdx.x;
    int chunk = (n + 1023) / 1024;
    int b = t * chunk;
    int en = b + chunk; if (en > n) en = n;
    int s = 0;
    for (int i = b; i < en; i++) s += g_cnt[i];
    ssum[t] = s;
    __syncthreads();
    if (!t) {
        int run = 0;
        for (int i = 0; i < 1024; i++) { int v = ssum[i]; ssum[i] = run; run += v; }
        g_off[n] = e;
        float sab = g_acc[0], sa2 = g_acc[1], sb2 = g_acc[2];
        float na = fmaxf(sqrtf(sa2), 1e-8f);
        float nb = fmaxf(sqrtf(sb2), 1e-8f);
        g_par[0] = expf(lambda0[0]);
        g_par[1] = gamma[0] * (sab / (na * nb));
    }
    __syncthreads();
    int run = ssum[t];
    for (int i = b; i < en; i++) {
        int v = g_cnt[i];
        g_off[i] = run;
        g_cnt[i] = run;  // cursor for the scatter pass
        run += v;
    }
}

// ---------------------------------------------------------------------------
// K3: counting-sort scatter of packed (col, adj) into row-sorted order.
// ---------------------------------------------------------------------------
__global__ void k_scatter(const int* __restrict__ row,
                          const int* __restrict__ col,
                          const float* __restrict__ adj, int e) {
    for (int i = blockIdx.x * blockDim.x + threadIdx.x; i < e;
         i += gridDim.x * blockDim.x) {
        int pos = atomicAdd(&g_cnt[row[i]], 1);
        g_edge[pos] = make_int2(col[i], __float_as_int(adj[i]));
    }
}

// ---------------------------------------------------------------------------
// K4: fused per-row kernel with BLOCKED 32-edge processing.
// One warp per destination row. For each block of <=32 edges:
//   1. lane computes 4-dim partial score p[i] for EVERY edge i in the block
//      (coalesced row loads of k/eigs, dozens of loads in flight),
//   2. log-depth warp transpose-reduce (31 pipelined shuffles per 32 edges)
//      leaves full score of edge l in lane l,
//   3. block max / exp / sum via once-per-block warp reductions (1 MUFU/edge),
//   4. independent-iteration v accumulation loop (no loop-carried chain).
// Online (flash-style) merge across blocks for both softmax branches.
// ---------------------------------------------------------------------------
__global__ void __launch_bounds__(256)
k_main(const float4* __restrict__ q4, const float4* __restrict__ k4p,
       const float4* __restrict__ v4p, const float* __restrict__ eigs,
       float4* __restrict__ out4, int n) {
    int wid  = (blockIdx.x * blockDim.x + threadIdx.x) >> 5;
    int lane = threadIdx.x & 31;
    if (wid >= n) return;
    int start = g_off[wid];
    int end   = g_off[wid + 1];
    float4 zero = make_float4(0.f, 0.f, 0.f, 0.f);
    if (start == end) {                 // empty segment -> zeros
        out4[wid * 32 + lane] = zero;
        return;
    }
    const float inv = 0.08838834764831845f;  // 1/sqrt(128)
    float c = g_par[1];

    float4 q = q4[wid * 32 + lane];
    float4 qs = make_float4(q.x * inv, q.y * inv, q.z * inv, q.w * inv);
    float  ler = g_par[0] * eigs[wid * 32 + lane];  // lambda * eig_r[lane]

    float  m0 = -INFINITY, z0 = 0.f;
    float  m1 = -INFINITY, z1 = 0.f;
    float4 a0 = zero, a1 = zero;

    for (int base = start; base < end; base += 32) {
        int nb = end - base; if (nb > 32) nb = 32;
        int2 ea = (lane < nb) ? g_edge[base + lane] : make_int2(0, 0);
        int   bc = ea.x;
        float ba = __int_as_float(ea.y);

        // ---- 1. per-lane partial scores for all edges of the block ----
        float p[32];
#pragma unroll
        for (int i = 0; i < 32; i++) {
            if (i < nb) {   // nb is warp-uniform -> uniform cheap branch
                int ci = __shfl_sync(FULLMASK, bc, i);
                float4 kk = k4p[ci * 32 + lane];
                float  ec = eigs[ci * 32 + lane];
                p[i] = fmaf(qs.x, kk.x,
                       fmaf(qs.y, kk.y,
                       fmaf(qs.z, kk.z,
                       fmaf(qs.w, kk.w, ler * ec))));
            } else {
                p[i] = 0.f;
            }
        }

        // ---- 2. butterfly transpose-reduce: lane l ends with score(edge l)
        float r16[16];
#pragma unroll
        for (int t = 0; t < 16; t++) {
            bool hi = (lane & 1);
            float mine = hi ? p[2 * t + 1] : p[2 * t];
            float oth  = hi ? p[2 * t]     : p[2 * t + 1];
            r16[t] = mine + __shfl_xor_sync(FULLMASK, oth, 1);
        }
        float r8[8];
#pragma unroll
        for (int t = 0; t < 8; t++) {
            bool hi = (lane & 2);
            float mine = hi ? r16[2 * t + 1] : r16[2 * t];
            float oth  = hi ? r16[2 * t]     : r16[2 * t + 1];
            r8[t] = mine + __shfl_xor_sync(FULLMASK, oth, 2);
        }
        float r4[4];
#pragma unroll
        for (int t = 0; t < 4; t++) {
            bool hi = (lane & 4);
            float mine = hi ? r8[2 * t + 1] : r8[2 * t];
            float oth  = hi ? r8[2 * t]     : r8[2 * t + 1];
            r4[t] = mine + __shfl_xor_sync(FULLMASK, oth, 4);
        }
        float r2[2];
#pragma unroll
        for (int t = 0; t < 2; t++) {
            bool hi = (lane & 8);
            float mine = hi ? r4[2 * t + 1] : r4[2 * t];
            float oth  = hi ? r4[2 * t]     : r4[2 * t + 1];
            r2[t] = mine + __shfl_xor_sync(FULLMASK, oth, 8);
        }
        float score;
        {
            bool hi = (lane & 16);
            float mine = hi ? r2[1] : r2[0];
            float oth  = hi ? r2[0] : r2[1];
            score = mine + __shfl_xor_sync(FULLMASK, oth, 16);
        }

        // ---- 3. block softmax stats + online merge (both branches) ----
        float s0 = (lane < nb) ? score  : -INFINITY;
        float s1 = (lane < nb) ? c * ba : -INFINITY;
        float bm0 = s0, bm1 = s1;
#pragma unroll
        for (int o = 16; o; o >>= 1) {
            bm0 = fmaxf(bm0, __shfl_xor_sync(FULLMASK, bm0, o));
            bm1 = fmaxf(bm1, __shfl_xor_sync(FULLMASK, bm1, o));
        }
        float nm0 = fmaxf(m0, bm0);
        float nm1 = fmaxf(m1, bm1);
        float w0 = __expf(s0 - nm0);   // exactly one exp per edge per branch
        float w1 = __expf(s1 - nm1);
        float sw0 = w0, sw1 = w1;
#pragma unroll
        for (int o = 16; o; o >>= 1) {
            sw0 += __shfl_xor_sync(FULLMASK, sw0, o);
            sw1 += __shfl_xor_sync(FULLMASK, sw1, o);
        }
        float sc0 = __expf(m0 - nm0);  // exp(-inf)=0 on first block
        float sc1 = __expf(m1 - nm1);
        z0 = fmaf(z0, sc0, sw0);
        z1 = fmaf(z1, sc1, sw1);
        a0.x *= sc0; a0.y *= sc0; a0.z *= sc0; a0.w *= sc0;
        a1.x *= sc1; a1.y *= sc1; a1.z *= sc1; a1.w *= sc1;
        m0 = nm0; m1 = nm1;

        // ---- 4. v accumulation: independent iterations, fully pipelined ----
#pragma unroll 8
        for (int i = 0; i < nb; i++) {
            int   ci  = __shfl_sync(FULLMASK, bc, i);
            float w0i = __shfl_sync(FULLMASK, w0, i);
            float w1i = __shfl_sync(FULLMASK, w1, i);
            float4 vv = v4p[ci * 32 + lane];
            a0.x = fmaf(w0i, vv.x, a0.x);
            a0.y = fmaf(w0i, vv.y, a0.y);
            a0.z = fmaf(w0i, vv.z, a0.z);
            a0.w = fmaf(w0i, vv.w, a0.w);
            a1.x = fmaf(w1i, vv.x, a1.x);
            a1.y = fmaf(w1i, vv.y, a1.y);
            a1.z = fmaf(w1i, vv.z, a1.z);
            a1.w = fmaf(w1i, vv.w, a1.w);
        }
    }

    float i0 = 0.5f / z0;
    float i1 = 0.5f / z1;
    float4 o;
    o.x = fmaf(a0.x, i0, a1.x * i1);
    o.y = fmaf(a0.y, i0, a1.y * i1);
    o.z = fmaf(a0.z, i0, a1.z * i1);
    o.w = fmaf(a0.w, i0, a1.w * i1);
    out4[wid * 32 + lane] = o;
}

// ---------------------------------------------------------------------------
extern "C" void kernel_launch(void* const* d_in, const int* in_sizes, int n_in,
                              void* d_out, int out_size) {
    const float* q       = (const float*)d_in[0];
    const float* k       = (const float*)d_in[1];
    const float* v       = (const float*)d_in[2];
    const float* eigs    = (const float*)d_in[3];
    const float* adj     = (const float*)d_in[4];
    const float* lambda0 = (const float*)d_in[5];
    const float* gamma   = (const float*)d_in[6];
    const float* memb    = (const float*)d_in[7];
    const int*   row     = (const int*)d_in[8];
    const int*   col     = (const int*)d_in[9];
    const int*   mids    = (const int*)d_in[10];

    int n = in_sizes[10];  // N
    int e = in_sizes[8];   // E

    k_init<<<(n + 255) / 256, 256>>>(memb, mids, n);
    k_edge1<<<2048, 256>>>(row, col, e);
    k_scan<<<1, 1024>>>(lambda0, gamma, n, e);
    k_scatter<<<2048, 256>>>(row, col, adj, e);
    k_main<<<(n * 32 + 255) / 256, 256>>>(
        (const float4*)q, (const float4*)k, (const float4*)v, eigs,
        (float4*)d_out, n);
}

// round 6
// speedup vs baseline: 1.1446x; 1.1446x over previous
#include <cuda_runtime.h>
#include <math.h>

// Problem-fixed sizes: N=100000, E=1600000, D=128, EIG=32.
#define MAXN 100000
#define MAXE 1600000
#define FULLMASK 0xffffffffu

// Scratch (device globals — explicitly zeroed by k_init every call).
__device__ float g_me[MAXN];        // per-node motif embedding value
__device__ int   g_cnt[MAXN];       // histogram, then scatter cursor
__device__ int   g_off[MAXN + 1];   // CSR row offsets
__device__ float g_acc[3];          // sum(ab), sum(a2), sum(b2)
__device__ float g_par[2];          // [0]=exp(lambda0), [1]=c = gamma*sim
__device__ int2  g_edge[MAXE];      // (col, adj-as-int) sorted by row

// ---------------------------------------------------------------------------
// K0: zero counters/accumulators, compute me[n] (R1/R2-proven protocol)
// ---------------------------------------------------------------------------
__global__ void k_init(const float* __restrict__ memb,
                       const int* __restrict__ mids, int n) {
    int i = blockIdx.x * blockDim.x + threadIdx.x;
    if (i == 0) { g_acc[0] = 0.f; g_acc[1] = 0.f; g_acc[2] = 0.f; }
    if (i < n) {
        g_me[i]  = memb[mids[i]];
        g_cnt[i] = 0;
    }
}

// ---------------------------------------------------------------------------
// K1: edge-level scalar reductions (cosine sim) + row histogram (R2 verbatim)
// ---------------------------------------------------------------------------
__global__ void k_edge1(const int* __restrict__ row,
                        const int* __restrict__ col, int e) {
    float pab = 0.f, pa2 = 0.f, pb2 = 0.f;
    for (int i = blockIdx.x * blockDim.x + threadIdx.x; i < e;
         i += gridDim.x * blockDim.x) {
        int r = row[i], c = col[i];
        atomicAdd(&g_cnt[r], 1);
        float a = g_me[r], b = g_me[c];
        pab = fmaf(a, b, pab);
        pa2 = fmaf(a, a, pa2);
        pb2 = fmaf(b, b, pb2);
    }
#pragma unroll
    for (int o = 16; o; o >>= 1) {
        pab += __shfl_down_sync(FULLMASK, pab, o);
        pa2 += __shfl_down_sync(FULLMASK, pa2, o);
        pb2 += __shfl_down_sync(FULLMASK, pb2, o);
    }
    __shared__ float sb[3][8];
    int w = threadIdx.x >> 5, l = threadIdx.x & 31;
    if (!l) { sb[0][w] = pab; sb[1][w] = pa2; sb[2][w] = pb2; }
    __syncthreads();
    if (!threadIdx.x) {
        float t0 = 0.f, t1 = 0.f, t2 = 0.f;
        int nw = blockDim.x >> 5;
        for (int j = 0; j < nw; j++) { t0 += sb[0][j]; t1 += sb[1][j]; t2 += sb[2][j]; }
        atomicAdd(&g_acc[0], t0);
        atomicAdd(&g_acc[1], t1);
        atomicAdd(&g_acc[2], t2);
    }
}

// ---------------------------------------------------------------------------
// K2: exclusive scan (R2-proven serial version — quarantining the rewrite
// until k_main is exonerated as the crash source)
// ---------------------------------------------------------------------------
__global__ void k_scan(const float* __restrict__ lambda0,
                       const float* __restrict__ gamma, int n, int e) {
    __shared__ int ssum[1024];
    int t = threadIdx.x;
    int chunk = (n + 1023) / 1024;
    int b = t * chunk;
    int en = b + chunk; if (en > n) en = n;
    int s = 0;
    for (int i = b; i < en; i++) s += g_cnt[i];
    ssum[t] = s;
    __syncthreads();
    if (!t) {
        int run = 0;
        for (int i = 0; i < 1024; i++) { int v = ssum[i]; ssum[i] = run; run += v; }
        g_off[n] = e;
        float sab = g_acc[0], sa2 = g_acc[1], sb2 = g_acc[2];
        float na = fmaxf(sqrtf(sa2), 1e-8f);
        float nb = fmaxf(sqrtf(sb2), 1e-8f);
        g_par[0] = expf(lambda0[0]);
        g_par[1] = gamma[0] * (sab / (na * nb));
    }
    __syncthreads();
    int run = ssum[t];
    for (int i = b; i < en; i++) {
        int v = g_cnt[i];
        g_off[i] = run;
        g_cnt[i] = run;  // cursor for the scatter pass
        run += v;
    }
}

// ---------------------------------------------------------------------------
// K3: counting-sort scatter, clamped write position (tripwire).
// ---------------------------------------------------------------------------
__global__ void k_scatter(const int* __restrict__ row,
                          const int* __restrict__ col,
                          const float* __restrict__ adj, int e) {
    for (int i = blockIdx.x * blockDim.x + threadIdx.x; i < e;
         i += gridDim.x * blockDim.x) {
        int pos = atomicAdd(&g_cnt[row[i]], 1);
        pos = min(max(pos, 0), MAXE - 1);
        g_edge[pos] = make_int2(col[i], __float_as_int(adj[i]));
    }
}

// ---------------------------------------------------------------------------
// K4: fused per-row kernel, 8-edge sub-blocks.
// FIXED vs R4/R5: all __shfl_sync are executed UNCONDITIONALLY by the full
// warp (the divergent-ternary shuffle is hoisted); every data-derived index
// (start/end, ci) is clamped so logic bugs surface as rel_err, not crashes.
// ---------------------------------------------------------------------------
__global__ void __launch_bounds__(256)
k_main(const float4* __restrict__ q4, const float4* __restrict__ k4p,
       const float4* __restrict__ v4p, const float* __restrict__ eigs,
       float4* __restrict__ out4, int n, int e) {
    int wid  = (blockIdx.x * blockDim.x + threadIdx.x) >> 5;
    int lane = threadIdx.x & 31;
    if (wid >= n) return;                 // warp-uniform
    int start = g_off[wid];
    int end   = g_off[wid + 1];
    start = min(max(start, 0), e);        // tripwire clamps
    end   = min(max(end, start), e);

    float4 zero = make_float4(0.f, 0.f, 0.f, 0.f);
    if (start == end) {                   // warp-uniform; zeros per reference
        out4[wid * 32 + lane] = zero;
        return;
    }
    const float inv = 0.08838834764831845f;  // 1/sqrt(128)
    float c = g_par[1];

    float4 q  = q4[wid * 32 + lane];
    float4 qs = make_float4(q.x * inv, q.y * inv, q.z * inv, q.w * inv);
    float  ler = g_par[0] * eigs[wid * 32 + lane];  // lambda * eig_r[lane]

    float  m0 = -INFINITY, z0 = 0.f;
    float  m1 = -INFINITY, z1 = 0.f;
    float4 a0 = zero, a1 = zero;

    int eidx = lane & 7;   // edge slot this lane owns after the reduce

    for (int base32 = start; base32 < end; base32 += 32) {
        int rem32 = end - base32; if (rem32 > 32) rem32 = 32;
        int2 ea = (lane < rem32) ? g_edge[base32 + lane] : make_int2(0, 0);
        int   bc = min(max(ea.x, 0), n - 1);   // clamp col (tripwire)
        float ba = __int_as_float(ea.y);

        for (int sub = 0; sub * 8 < rem32; sub++) {   // warp-uniform trip count
            int nb = rem32 - sub * 8; if (nb > 8) nb = 8;

            // ---- 1. partial scores: shuffles unconditional, loads guarded
            //         by the warp-UNIFORM i<nb ----
            float p[8];
#pragma unroll
            for (int i = 0; i < 8; i++) {
                int ci = __shfl_sync(FULLMASK, bc, sub * 8 + i);  // full warp
                if (i < nb) {
                    float4 kk = k4p[ci * 32 + lane];
                    float  ec = eigs[ci * 32 + lane];
                    p[i] = fmaf(qs.x, kk.x,
                           fmaf(qs.y, kk.y,
                           fmaf(qs.z, kk.z,
                           fmaf(qs.w, kk.w, ler * ec))));
                } else {
                    p[i] = 0.f;
                }
            }

            // ---- 2. transpose-reduce: lane l -> full score of edge (l&7) ----
            bool b0 = lane & 1, b1 = lane & 2, b2 = lane & 4;
            float r4[4];
#pragma unroll
            for (int t = 0; t < 4; t++) {
                float mine = b0 ? p[2 * t + 1] : p[2 * t];
                float oth  = b0 ? p[2 * t]     : p[2 * t + 1];
                r4[t] = mine + __shfl_xor_sync(FULLMASK, oth, 1);
            }
            float r2[2];
#pragma unroll
            for (int t = 0; t < 2; t++) {
                float mine = b1 ? r4[2 * t + 1] : r4[2 * t];
                float oth  = b1 ? r4[2 * t]     : r4[2 * t + 1];
                r2[t] = mine + __shfl_xor_sync(FULLMASK, oth, 2);
            }
            float mine = b2 ? r2[1] : r2[0];
            float oth  = b2 ? r2[0] : r2[1];
            float sc   = mine + __shfl_xor_sync(FULLMASK, oth, 4);
            sc += __shfl_xor_sync(FULLMASK, sc, 8);
            sc += __shfl_xor_sync(FULLMASK, sc, 16);
            // sc = score(edge eidx), replicated across the four 8-lane groups

            // ---- 3. block stats — shuffle HOISTED out of the divergent
            //         ternary (this was the R4/R5 UB) ----
            float ba_e = __shfl_sync(FULLMASK, ba, sub * 8 + eidx);  // full warp
            bool valid = eidx < nb;
            float s0 = valid ? sc       : -INFINITY;
            float s1 = valid ? c * ba_e : -INFINITY;
            float bm0 = s0, bm1 = s1;
#pragma unroll
            for (int o = 1; o < 8; o <<= 1) {
                bm0 = fmaxf(bm0, __shfl_xor_sync(FULLMASK, bm0, o));
                bm1 = fmaxf(bm1, __shfl_xor_sync(FULLMASK, bm1, o));
            }
            // ---- 4. online merge ----
            float nm0 = fmaxf(m0, bm0);
            float nm1 = fmaxf(m1, bm1);
            float w0 = __expf(s0 - nm0);   // 0 for invalid slots
            float w1 = __expf(s1 - nm1);
            float sw0 = w0, sw1 = w1;
#pragma unroll
            for (int o = 1; o < 8; o <<= 1) {
                sw0 += __shfl_xor_sync(FULLMASK, sw0, o);
                sw1 += __shfl_xor_sync(FULLMASK, sw1, o);
            }
            float f0 = __expf(m0 - nm0);   // 0 on first block
            float f1 = __expf(m1 - nm1);
            z0 = fmaf(z0, f0, sw0);
            z1 = fmaf(z1, f1, sw1);
            a0.x *= f0; a0.y *= f0; a0.z *= f0; a0.w *= f0;
            a1.x *= f1; a1.y *= f1; a1.z *= f1; a1.w *= f1;
            m0 = nm0; m1 = nm1;

            // ---- 5. v accumulation: shuffles unconditional, load guarded
            //         by warp-uniform i<nb ----
#pragma unroll
            for (int i = 0; i < 8; i++) {
                int   ci  = __shfl_sync(FULLMASK, bc, sub * 8 + i);
                float w0i = __shfl_sync(FULLMASK, w0, i);  // lane i owns edge i
                float w1i = __shfl_sync(FULLMASK, w1, i);
                if (i < nb) {
                    float4 vv = v4p[ci * 32 + lane];
                    a0.x = fmaf(w0i, vv.x, a0.x);
                    a0.y = fmaf(w0i, vv.y, a0.y);
                    a0.z = fmaf(w0i, vv.z, a0.z);
                    a0.w = fmaf(w0i, vv.w, a0.w);
                    a1.x = fmaf(w1i, vv.x, a1.x);
                    a1.y = fmaf(w1i, vv.y, a1.y);
                    a1.z = fmaf(w1i, vv.z, a1.z);
                    a1.w = fmaf(w1i, vv.w, a1.w);
                }
            }
        }
    }

    float i0 = 0.5f / z0;
    float i1 = 0.5f / z1;
    float4 o;
    o.x = fmaf(a0.x, i0, a1.x * i1);
    o.y = fmaf(a0.y, i0, a1.y * i1);
    o.z = fmaf(a0.z, i0, a1.z * i1);
    o.w = fmaf(a0.w, i0, a1.w * i1);
    out4[wid * 32 + lane] = o;
}

// ---------------------------------------------------------------------------
extern "C" void kernel_launch(void* const* d_in, const int* in_sizes, int n_in,
                              void* d_out, int out_size) {
    const float* q       = (const float*)d_in[0];
    const float* k       = (const float*)d_in[1];
    const float* v       = (const float*)d_in[2];
    const float* eigs    = (const float*)d_in[3];
    const float* adj     = (const float*)d_in[4];
    const float* lambda0 = (const float*)d_in[5];
    const float* gamma   = (const float*)d_in[6];
    const float* memb    = (const float*)d_in[7];
    const int*   row     = (const int*)d_in[8];
    const int*   col     = (const int*)d_in[9];
    const int*   mids    = (const int*)d_in[10];

    int n = in_sizes[10];  // N
    int e = in_sizes[8];   // E

    k_init<<<(n + 255) / 256, 256>>>(memb, mids, n);
    k_edge1<<<2048, 256>>>(row, col, e);
    k_scan<<<1, 1024>>>(lambda0, gamma, n, e);
    k_scatter<<<2048, 256>>>(row, col, adj, e);
    k_main<<<(n * 32 + 255) / 256, 256>>>(
        (const float4*)q, (const float4*)k, (const float4*)v, eigs,
        (float4*)d_out, n, e);
}

// round 8
// speedup vs baseline: 1.3291x; 1.1612x over previous
#include <cuda_runtime.h>
#include <cuda_fp16.h>
#include <math.h>

// Problem-fixed sizes: N=100000, E=1600000, D=128, EIG=32.
#define MAXN 100000
#define MAXE 1600000
#define FULLMASK 0xffffffffu

// Scratch (device globals — explicitly zeroed by k_init every call).
__device__ float g_me[MAXN];        // per-node motif embedding value
__device__ int   g_cnt[MAXN];       // histogram, then scatter cursor
__device__ int   g_off[MAXN + 1];   // CSR row offsets
__device__ float g_acc[3];          // sum(ab), sum(a2), sum(b2)
__device__ float g_par[2];          // [0]=exp(lambda0), [1]=c = gamma*sim
__device__ int2  g_edge[MAXE];      // (col, adj-as-int) sorted by row
__device__ uint2 g_vh[MAXN * 32];   // v packed as fp16 (4 halfs per uint2)

// ---- cache-policy-steered load helpers (createpolicy + cache_hint form,
// the sm_103a-legal encoding for evict_last at any width) ----
__device__ __forceinline__ unsigned long long mk_policy_el() {
    unsigned long long pol;
    asm("createpolicy.fractional.L2::evict_last.b64 %0, 1.0;" : "=l"(pol));
    return pol;
}
__device__ __forceinline__ float4 ldg_el_f4(const float4* p,
                                            unsigned long long pol) {
    float4 r;
    asm("ld.global.nc.L2::cache_hint.v4.f32 {%0,%1,%2,%3},[%4],%5;"
        : "=f"(r.x), "=f"(r.y), "=f"(r.z), "=f"(r.w) : "l"(p), "l"(pol));
    return r;
}
__device__ __forceinline__ float ldg_el_f(const float* p,
                                          unsigned long long pol) {
    float r;
    asm("ld.global.nc.L2::cache_hint.f32 %0,[%1],%2;" : "=f"(r)
        : "l"(p), "l"(pol));
    return r;
}
__device__ __forceinline__ uint2 ldg_el_u2(const uint2* p,
                                           unsigned long long pol) {
    uint2 r;
    asm("ld.global.nc.L2::cache_hint.v2.u32 {%0,%1},[%2],%3;"
        : "=r"(r.x), "=r"(r.y) : "l"(p), "l"(pol));
    return r;
}

// ---------------------------------------------------------------------------
// K0: zero counters/accumulators, compute me[n] (proven protocol)
// ---------------------------------------------------------------------------
__global__ void k_init(const float* __restrict__ memb,
                       const int* __restrict__ mids, int n) {
    int i = blockIdx.x * blockDim.x + threadIdx.x;
    if (i == 0) { g_acc[0] = 0.f; g_acc[1] = 0.f; g_acc[2] = 0.f; }
    if (i < n) {
        g_me[i]  = memb[__ldcs(&mids[i])];
        g_cnt[i] = 0;
    }
}

// ---------------------------------------------------------------------------
// K0b: pack v into fp16 (streaming read/write)
// ---------------------------------------------------------------------------
__global__ void k_pack(const float4* __restrict__ v4, int n32) {
    for (int i = blockIdx.x * blockDim.x + threadIdx.x; i < n32;
         i += gridDim.x * blockDim.x) {
        float4 vv = __ldcs(&v4[i]);
        __half2 h0 = __floats2half2_rn(vv.x, vv.y);
        __half2 h1 = __floats2half2_rn(vv.z, vv.w);
        uint2 u;
        u.x = *reinterpret_cast<unsigned*>(&h0);
        u.y = *reinterpret_cast<unsigned*>(&h1);
        g_vh[i] = u;
    }
}

// ---------------------------------------------------------------------------
// K1: edge-level scalar reductions (cosine sim) + row histogram
// ---------------------------------------------------------------------------
__global__ void k_edge1(const int* __restrict__ row,
                        const int* __restrict__ col, int e) {
    float pab = 0.f, pa2 = 0.f, pb2 = 0.f;
    for (int i = blockIdx.x * blockDim.x + threadIdx.x; i < e;
         i += gridDim.x * blockDim.x) {
        int r = __ldcs(&row[i]), c = __ldcs(&col[i]);
        atomicAdd(&g_cnt[r], 1);
        float a = g_me[r], b = g_me[c];
        pab = fmaf(a, b, pab);
        pa2 = fmaf(a, a, pa2);
        pb2 = fmaf(b, b, pb2);
    }
#pragma unroll
    for (int o = 16; o; o >>= 1) {
        pab += __shfl_down_sync(FULLMASK, pab, o);
        pa2 += __shfl_down_sync(FULLMASK, pa2, o);
        pb2 += __shfl_down_sync(FULLMASK, pb2, o);
    }
    __shared__ float sb[3][8];
    int w = threadIdx.x >> 5, l = threadIdx.x & 31;
    if (!l) { sb[0][w] = pab; sb[1][w] = pa2; sb[2][w] = pb2; }
    __syncthreads();
    if (!threadIdx.x) {
        float t0 = 0.f, t1 = 0.f, t2 = 0.f;
        int nw = blockDim.x >> 5;
        for (int j = 0; j < nw; j++) { t0 += sb[0][j]; t1 += sb[1][j]; t2 += sb[2][j]; }
        atomicAdd(&g_acc[0], t0);
        atomicAdd(&g_acc[1], t1);
        atomicAdd(&g_acc[2], t2);
    }
}

// ---------------------------------------------------------------------------
// K2: exclusive scan (R2-proven serial version)
// ---------------------------------------------------------------------------
__global__ void k_scan(const float* __restrict__ lambda0,
                       const float* __restrict__ gamma, int n, int e) {
    __shared__ int ssum[1024];
    int t = threadIdx.x;
    int chunk = (n + 1023) / 1024;
    int b = t * chunk;
    int en = b + chunk; if (en > n) en = n;
    int s = 0;
    for (int i = b; i < en; i++) s += g_cnt[i];
    ssum[t] = s;
    __syncthreads();
    if (!t) {
        int run = 0;
        for (int i = 0; i < 1024; i++) { int v = ssum[i]; ssum[i] = run; run += v; }
        g_off[n] = e;
        float sab = g_acc[0], sa2 = g_acc[1], sb2 = g_acc[2];
        float na = fmaxf(sqrtf(sa2), 1e-8f);
        float nb = fmaxf(sqrtf(sb2), 1e-8f);
        g_par[0] = expf(lambda0[0]);
        g_par[1] = gamma[0] * (sab / (na * nb));
    }
    __syncthreads();
    int run = ssum[t];
    for (int i = b; i < en; i++) {
        int v = g_cnt[i];
        g_off[i] = run;
        g_cnt[i] = run;  // cursor for the scatter pass
        run += v;
    }
}

// ---------------------------------------------------------------------------
// K3: counting-sort scatter, clamped write position (tripwire).
// ---------------------------------------------------------------------------
__global__ void k_scatter(const int* __restrict__ row,
                          const int* __restrict__ col,
                          const float* __restrict__ adj, int e) {
    for (int i = blockIdx.x * blockDim.x + threadIdx.x; i < e;
         i += gridDim.x * blockDim.x) {
        int pos = atomicAdd(&g_cnt[__ldcs(&row[i])], 1);
        pos = min(max(pos, 0), MAXE - 1);
        g_edge[pos] = make_int2(__ldcs(&col[i]), __float_as_int(__ldcs(&adj[i])));
    }
}

// ---------------------------------------------------------------------------
// K4: fused per-row kernel (R2-proven structure) with L2-steered gathers:
// k/eigs/v-fp16 gathers use evict_last policy (footprint 51+12.8+25.6=90MB
// < 126MB L2); single-use streams (q, g_edge, out) use cs hints so they
// cannot evict the resident gather set.
// ---------------------------------------------------------------------------
__global__ void __launch_bounds__(256)
k_main(const float4* __restrict__ q4, const float4* __restrict__ k4p,
       const float* __restrict__ eigs, float4* __restrict__ out4,
       int n, int e) {
    int wid  = (blockIdx.x * blockDim.x + threadIdx.x) >> 5;
    int lane = threadIdx.x & 31;
    if (wid >= n) return;
    int start = g_off[wid];
    int end   = g_off[wid + 1];
    start = min(max(start, 0), e);
    end   = min(max(end, start), e);

    float4 zero = make_float4(0.f, 0.f, 0.f, 0.f);
    if (start == end) {                 // empty segment -> zeros
        out4[wid * 32 + lane] = zero;
        return;
    }
    unsigned long long pol = mk_policy_el();
    const float inv = 0.08838834764831845f;  // 1/sqrt(128)
    float c = g_par[1];

    float4 q  = __ldcs(&q4[wid * 32 + lane]);           // single-use stream
    float4 qs = make_float4(q.x * inv, q.y * inv, q.z * inv, q.w * inv);
    float  ler = g_par[0] * ldg_el_f(&eigs[wid * 32 + lane], pol);

    float  m0 = -INFINITY, z0 = 0.f;
    float  m1 = -INFINITY, z1 = 0.f;
    float4 a0 = zero, a1 = zero;

    for (int base = start; base < end; base += 32) {
        int nb = end - base; if (nb > 32) nb = 32;
        int2 ea = (lane < nb) ? __ldcs(&g_edge[base + lane]) : make_int2(0, 0);
        int   bc = min(max(ea.x, 0), n - 1);
        float ba = __int_as_float(ea.y);

        // depth-1 software pipeline (R2 structure)
        int    ci = __shfl_sync(FULLMASK, bc, 0);
        float4 kk = ldg_el_f4(&k4p[ci * 32 + lane], pol);
        float  ec = ldg_el_f(&eigs[ci * 32 + lane], pol);
        uint2  vu = ldg_el_u2(&g_vh[ci * 32 + lane], pol);

        for (int i = 0; i < nb; i++) {
            int j = i + 1; if (j >= nb) j = i;
            int    cn  = __shfl_sync(FULLMASK, bc, j);
            float  adj = __shfl_sync(FULLMASK, ba, i);
            float4 kk2 = ldg_el_f4(&k4p[cn * 32 + lane], pol);
            float  ec2 = ldg_el_f(&eigs[cn * 32 + lane], pol);
            uint2  vu2 = ldg_el_u2(&g_vh[cn * 32 + lane], pol);

            float part = fmaf(qs.x, kk.x,
                         fmaf(qs.y, kk.y,
                         fmaf(qs.z, kk.z,
                         fmaf(qs.w, kk.w, ler * ec))));
#pragma unroll
            for (int o = 16; o; o >>= 1)
                part += __shfl_xor_sync(FULLMASK, part, o);

            // unpack fp16 v
            __half2 h0 = *reinterpret_cast<__half2*>(&vu.x);
            __half2 h1 = *reinterpret_cast<__half2*>(&vu.y);
            float2 v01 = __half22float2(h0);
            float2 v23 = __half22float2(h1);

            // branch 0: online softmax of s0
            float nm0 = fmaxf(m0, part);
            float sc0 = __expf(m0 - nm0);
            float w0  = __expf(part - nm0);
            z0   = fmaf(z0, sc0, w0);
            a0.x = fmaf(a0.x, sc0, w0 * v01.x);
            a0.y = fmaf(a0.y, sc0, w0 * v01.y);
            a0.z = fmaf(a0.z, sc0, w0 * v23.x);
            a0.w = fmaf(a0.w, sc0, w0 * v23.y);
            m0 = nm0;

            // branch 1: online softmax of c*adj
            float s1  = c * adj;
            float nm1 = fmaxf(m1, s1);
            float sc1 = __expf(m1 - nm1);
            float w1  = __expf(s1 - nm1);
            z1   = fmaf(z1, sc1, w1);
            a1.x = fmaf(a1.x, sc1, w1 * v01.x);
            a1.y = fmaf(a1.y, sc1, w1 * v01.y);
            a1.z = fmaf(a1.z, sc1, w1 * v23.x);
            a1.w = fmaf(a1.w, sc1, w1 * v23.y);
            m1 = nm1;

            kk = kk2; ec = ec2; vu = vu2;
        }
    }

    float i0 = 0.5f / z0;
    float i1 = 0.5f / z1;
    float4 o;
    o.x = fmaf(a0.x, i0, a1.x * i1);
    o.y = fmaf(a0.y, i0, a1.y * i1);
    o.z = fmaf(a0.z, i0, a1.z * i1);
    o.w = fmaf(a0.w, i0, a1.w * i1);
    __stcs(&out4[wid * 32 + lane], o);
}

// ---------------------------------------------------------------------------
extern "C" void kernel_launch(void* const* d_in, const int* in_sizes, int n_in,
                              void* d_out, int out_size) {
    const float* q       = (const float*)d_in[0];
    const float* k       = (const float*)d_in[1];
    const float* v       = (const float*)d_in[2];
    const float* eigs    = (const float*)d_in[3];
    const float* adj     = (const float*)d_in[4];
    const float* lambda0 = (const float*)d_in[5];
    const float* gamma   = (const float*)d_in[6];
    const float* memb    = (const float*)d_in[7];
    const int*   row     = (const int*)d_in[8];
    const int*   col     = (const int*)d_in[9];
    const int*   mids    = (const int*)d_in[10];

    int n = in_sizes[10];  // N
    int e = in_sizes[8];   // E

    k_init<<<(n + 255) / 256, 256>>>(memb, mids, n);
    k_pack<<<2048, 256>>>((const float4*)v, n * 32);
    k_edge1<<<2048, 256>>>(row, col, e);
    k_scan<<<1, 1024>>>(lambda0, gamma, n, e);
    k_scatter<<<2048, 256>>>(row, col, adj, e);
    k_main<<<(n * 32 + 255) / 256, 256>>>(
        (const float4*)q, (const float4*)k, eigs,
        (float4*)d_out, n, e);
}